// round 14
// baseline (speedup 1.0000x reference)
#include <cuda_runtime.h>
#include <cuda_bf16.h>
#include <cstdint>

// TemporalCooccurrenceMatrix — round 14: once-per-position precompute.
// prep (1 warp per walk): exps (e^{+t/5},e^{-t/5}) -> g_e2, per-walk 32-word
// node bitmask table -> g_nm, per-quarter packed node values (5x6b, mask
// folded as 32) -> g_vkp. cooc is then a pure pair loop: 6 LDGs per thread,
// table LDG->STS, no layout selects, no MUFU except dvals/tanh.
//
// C[b,w1,w2] = sum_{l1,l2} [node==][mask&mask] * e^{-(l1-l2)^2/4}*e^{-|t1-t2|/5}
// out = tanh(min(C,10)); symmetric -> rows r and 127-r paired per CTA.
// e^{-|a-b|/5} = min(e^{a/5}e^{-b/5}, e^{-a/5}e^{b/5}).

#define NWALK 1024            // 8*128
#define BDIM  576             // 4 threads x 129 targets = 516 active

__device__ __align__(16) float2       g_e2 [NWALK * 20];  // (e^{+t/5}, e^{-t/5})
__device__              unsigned int g_nm [NWALK * 32];  // node bitmask tables
__device__              unsigned int g_vkp[NWALK * 4];   // packed 5x6b per quarter

__device__ __forceinline__ float tanh_approx(float x) {
    float r;
    asm("tanh.approx.f32 %0, %1;" : "=f"(r) : "f"(x));
    return r;
}

// ---------------- prep: one warp per walk ----------------
__global__ __launch_bounds__(256)
void prep_kernel(const void* __restrict__ nodes_raw,
                 const void* __restrict__ masks_raw,
                 const float* __restrict__ times)
{
    __shared__ int s_n64, s_m32;
    __shared__ unsigned int tbl[8][32];

    const int tid  = threadIdx.x;
    const int wp   = tid >> 5;
    const int lane = tid & 31;

    if (tid < 32) {                              // dtype detection, one round trip
        const unsigned int*  nw = (const unsigned int*)nodes_raw;
        const unsigned char* mb = (const unsigned char*)masks_raw;
        unsigned int oddw = nw[2 * tid + 1];              // int64 LE hi words all 0
        unsigned char b0 = mb[tid], b1 = mb[32 + tid];    // int32-bool: k%4!=0 zero
        int nviol = (oddw != 0u);
        int mviol = (((tid & 3) != 0) && b0 != 0) |
                    ((((32 + tid) & 3) != 0) && b1 != 0);
        unsigned int vn = __ballot_sync(0xFFFFFFFFu, nviol);
        unsigned int vm = __ballot_sync(0xFFFFFFFFu, mviol);
        if (tid == 0) { s_n64 = (vn == 0u); s_m32 = (vm == 0u); }
    }
    tbl[wp][lane] = 0u;
    __syncthreads();

    const int walk = blockIdx.x * 8 + wp;        // 0..1023 (global: b*128 + w)
    const int n64 = s_n64, m32 = s_m32;
    const unsigned int*  n32p = (const unsigned int*)nodes_raw;
    const unsigned char* mbp  = (const unsigned char*)masks_raw;
    const unsigned int*  m32p = (const unsigned int*)masks_raw;

    unsigned int vs = 32u;                       // this lane's value (32 = invalid)
    if (lane < 20) {
        const int i = walk * 20 + lane;
        int  v = (int)(n64 ? n32p[i * 2] : n32p[i]) & 31;
        bool m = m32 ? (m32p[i] != 0u) : (mbp[i] != 0);
        float t = times[i] * 0.2f;
        g_e2[i] = make_float2(__expf(t), __expf(-t));
        if (m) atomicOr(&tbl[wp][v], 1u << lane);
        vs = m ? (unsigned int)v : 32u;
    }
    __syncwarp();

    // pack quarters: lane q (0..3) gathers values of positions q*5..q*5+4
    unsigned int pk = 0u;
#pragma unroll
    for (int mI = 0; mI < 5; mI++) {
        unsigned int vv = __shfl_sync(0xFFFFFFFFu, vs, (lane * 5 + mI) & 31);
        pk |= (vv & 63u) << (6 * mI);
    }
    if (lane < 4) g_vkp[walk * 4 + lane] = pk;
    g_nm[walk * 32 + lane] = tbl[wp][lane];
}

// ---------------- cooc: pure pair loop ----------------
__global__ __launch_bounds__(BDIM, 3)
void cooc_kernel(float* __restrict__ out)
{
    const int r   = blockIdx.x;   // 0..63
    const int b   = blockIdx.y;   // 0..7
    const int tid = threadIdx.x;

    const int wA = r, wB = 127 - r;
    const int nA = 128 - r;       // row-A targets (w2 in [r,127]); nB = r+1

    __shared__ float        dvals[32];          // exp(-d^2/4), 0 for d>=20
    __shared__ unsigned int nmA[33], nmB[33];   // [32] stays 0 (sentinel)
    __shared__ float2       sA[32], sB[32];     // entries >=20 are (0,0)

    // ---- target identity + independent prefetch (before smem section) ----
    const int  pair    = tid >> 2;              // 0..143 (129 real)
    const int  quarter = tid & 3;
    const bool active  = (pair < 129);
    const bool rowA    = active ? (pair < nA) : true;
    int w2 = rowA ? (wA + (active ? pair : 0)) : (wB + (pair - nA));
    if (!active) w2 = 127;                      // safe addresses, result discarded
    const int gw2 = b * 128 + w2;

    const unsigned int vkpack = g_vkp[gw2 * 4 + quarter];
    float2 e[5];
    {
        const float2* ep = g_e2 + gw2 * 20 + quarter * 5;
#pragma unroll
        for (int k = 0; k < 5; k++) e[k] = ep[k];
    }

    // ---- smem fill (disjoint thread ranges, all plain LDG->STS) ----
    if (tid < 32)
        dvals[tid] = (tid < 20) ? __expf(-0.25f * (float)(tid * tid)) : 0.0f;
    else if (tid >= 64 && tid < 96)
        nmA[tid - 64] = g_nm[(b * 128 + wA) * 32 + (tid - 64)];
    else if (tid >= 96 && tid < 128)
        nmB[tid - 96] = g_nm[(b * 128 + wB) * 32 + (tid - 96)];
    else if (tid >= 128 && tid < 148)
        sA[tid - 128] = g_e2[(b * 128 + wA) * 20 + (tid - 128)];
    else if (tid >= 148 && tid < 168)
        sB[tid - 148] = g_e2[(b * 128 + wB) * 20 + (tid - 148)];
    else if (tid >= 168 && tid < 180)
        sA[20 + tid - 168] = make_float2(0.0f, 0.0f);
    else if (tid >= 180 && tid < 192)
        sB[20 + tid - 180] = make_float2(0.0f, 0.0f);
    else if (tid == 192) nmA[32] = 0u;
    else if (tid == 193) nmB[32] = 0u;
    __syncthreads();

    // ---- phase C: predicated 2-slot loop, single deferred rare path ----
    const unsigned int* NM = rowA ? nmA : nmB;
    const float2*       S  = rowA ? sA  : sB;
    const int ljbase = quarter * 5;

    float a0 = 0.0f, a1 = 0.0f;
    unsigned int restflags = 0u;
#pragma unroll
    for (int k = 0; k < 5; k++) {
        const unsigned int vkk = (vkpack >> (6 * k)) & 63u;
        unsigned int bits = NM[vkk];
        const float exk = e[k].x, eyk = e[k].y;
        const int lj = ljbase + k;

        int li0 = __ffs(bits) - 1;               // empty -> -1 -> S[31]=(0,0)
        unsigned int b1m = bits & (bits - 1);
        int li1 = __ffs(b1m) - 1;
        restflags |= (b1m & (b1m - 1)) ? (1u << k) : 0u;
        {
            float2 sv = S[li0 & 31];
            int d = li0 - lj; d = d < 0 ? -d : d;
            a0 += dvals[d] * fminf(exk * sv.y, eyk * sv.x);
        }
        {
            float2 sv = S[li1 & 31];
            int d = li1 - lj; d = d < 0 ? -d : d;
            a1 += dvals[d] * fminf(exk * sv.y, eyk * sv.x);
        }
    }

    if (restflags) {                             // multiplicity >= 3 (rare)
#pragma unroll 1
        do {
            int k = __ffs(restflags) - 1;
            restflags &= restflags - 1;
            const unsigned int vkk = (vkpack >> (6 * k)) & 63u;
            unsigned int bits = NM[vkk];
            bits &= bits - 1;                    // drop slot 0
            bits &= bits - 1;                    // drop slot 1
            const float exk = e[k].x, eyk = e[k].y;
            const int lj = ljbase + k;
#pragma unroll 1
            do {
                int li = __ffs(bits) - 1;
                bits &= bits - 1;
                float2 sv = S[li];
                int d = li - lj; d = d < 0 ? -d : d;
                a0 += dvals[d] * fminf(exk * sv.y, eyk * sv.x);
            } while (bits);
        } while (restflags);
    }

    // ---- combine 4 lanes per target, tanh, symmetric store ----
    float a = a0 + a1;
    a += __shfl_xor_sync(0xFFFFFFFFu, a, 1);
    a += __shfl_xor_sync(0xFFFFFFFFu, a, 2);
    if (active && quarter == 0) {
        const int w1 = rowA ? wA : wB;
        float v = tanh_approx(fminf(a, 10.0f));  // a >= 0; approx err ~1e-4
        out[(b * 128 + w1) * 128 + w2] = v;
        out[(b * 128 + w2) * 128 + w1] = v;
    }
}

extern "C" void kernel_launch(void* const* d_in, const int* in_sizes, int n_in,
                              void* d_out, int out_size)
{
    const void*  nodes = d_in[0];
    const void*  masks = d_in[1];
    const float* times = (const float*)d_in[2];
    float*       out   = (float*)d_out;

    prep_kernel<<<NWALK / 8, 256>>>(nodes, masks, times);
    dim3 grid(64, 8);
    cooc_kernel<<<grid, BDIM>>>(out);
}

// round 15
// speedup vs baseline: 1.1813x; 1.1813x over previous
#include <cuda_runtime.h>
#include <cuda_bf16.h>
#include <cstdint>

// TemporalCooccurrenceMatrix — round 15: single fused kernel, R9 shape
// (2 threads/target, BDIM 288) + R13 lean inner loop.
// Evidence: single-kernel always beats split (no 2-3us gap tax); R9's
// 2-thr/target shape had the best measured phase C (9.06us).
//
// C[b,w1,w2] = sum_{l1,l2} [node==][mask&mask] * e^{-(l1-l2)^2/4}*e^{-|t1-t2|/5}
// out = tanh(min(C,10)); symmetric -> rows r and 127-r paired per CTA (512 CTAs).
// e^{-|a-b|/5} = min(e^{a/5}e^{-b/5}, e^{-a/5}e^{b/5}).

#define BDIM 288              // 2 threads x 129 targets = 258 active

__device__ __forceinline__ float tanh_approx(float x) {
    float r;
    asm("tanh.approx.f32 %0, %1;" : "=f"(r) : "f"(x));
    return r;
}

__global__ __launch_bounds__(BDIM)
void cooc_fused(const void* __restrict__ nodes_raw,
                const void* __restrict__ masks_raw,
                const float* __restrict__ times,
                float* __restrict__ out)
{
    const int r   = blockIdx.x;   // 0..63
    const int b   = blockIdx.y;   // 0..7
    const int tid = threadIdx.x;

    const int wA = r, wB = 127 - r;
    const int nA = 128 - r;       // row-A targets (w2 in [r,127]); nB = r+1

    __shared__ float        dvals[32];          // exp(-d^2/4), 0 for d>=20
    __shared__ unsigned int nmA[33], nmB[33];   // [32] stays 0 (sentinel)
    __shared__ float2       sA[32], sB[32];     // entries >=20 are (0,0)
    __shared__ int          s_n64, s_m32;

    // ---- target identity ----
    const int  pair   = tid >> 1;               // 0..143 (129 real)
    const int  half   = tid & 1;
    const bool active = (pair < 129);
    const bool rowA   = active ? (pair < nA) : true;
    int w2 = rowA ? (wA + (active ? pair : 0)) : (wB + (pair - nA));
    if (!active) w2 = 127;                      // safe addresses, result discarded
    const int jbase = (b * 128 + w2) * 20 + half * 10;

    // ---- phase A: detection + smem init + independent time prefetch ----
    if (tid < 32) {                             // warp 0: dtype detection
        const unsigned int*  nw = (const unsigned int*)nodes_raw;
        const unsigned char* mb = (const unsigned char*)masks_raw;
        unsigned int oddw = nw[2 * tid + 1];             // int64 LE hi words all 0
        unsigned char b0 = mb[tid], b1 = mb[32 + tid];   // int32-bool: k%4!=0 zero
        int nviol = (oddw != 0u);
        int mviol = (((tid & 3) != 0) && b0 != 0) |
                    ((((32 + tid) & 3) != 0) && b1 != 0);
        unsigned int vn = __ballot_sync(0xFFFFFFFFu, nviol);
        unsigned int vm = __ballot_sync(0xFFFFFFFFu, mviol);
        if (tid == 0) { s_n64 = (vn == 0u); s_m32 = (vm == 0u); }
    }
    if (tid >= 64  && tid < 96)  dvals[tid - 64] =
        (tid - 64 < 20) ? __expf(-0.25f * (float)((tid - 64) * (tid - 64))) : 0.0f;
    if (tid >= 96  && tid < 129) nmA[tid - 96]  = 0u;
    if (tid >= 129 && tid < 162) nmB[tid - 129] = 0u;
    if (tid >= 162 && tid < 174) sA[20 + tid - 162] = make_float2(0.0f, 0.0f);
    if (tid >= 174 && tid < 186) sB[20 + tid - 174] = make_float2(0.0f, 0.0f);

    // target times: 10 floats, 8B-aligned -> 5 independent LDG.64 (MLP)
    float2 t2[5];
    {
        const float2* tp = (const float2*)(times + jbase);
#pragma unroll
        for (int q = 0; q < 5; q++) t2[q] = tp[q];
    }
    __syncthreads();

    const int n64 = s_n64, m32 = s_m32;
    const unsigned int*  n32p = (const unsigned int*)nodes_raw;
    const unsigned char* mbp  = (const unsigned char*)masks_raw;
    const unsigned int*  m32p = (const unsigned int*)masks_raw;

    // ---- phase B: row tables + packed target node/mask + target exps ----
    if (tid < 20) {
        const int i = (b * 128 + wA) * 20 + tid;
        int  v = (int)(n64 ? n32p[i * 2] : n32p[i]) & 31;
        bool m = m32 ? (m32p[i] != 0u) : (mbp[i] != 0);
        float t = times[i] * 0.2f;
        sA[tid] = make_float2(__expf(t), __expf(-t));
        if (m) atomicOr(&nmA[v], 1u << tid);
    } else if (tid >= 32 && tid < 52) {
        const int l = tid - 32;
        const int i = (b * 128 + wB) * 20 + l;
        int  v = (int)(n64 ? n32p[i * 2] : n32p[i]) & 31;
        bool m = m32 ? (m32p[i] != 0u) : (mbp[i] != 0);
        float t = times[i] * 0.2f;
        sB[l] = make_float2(__expf(t), __expf(-t));
        if (m) atomicOr(&nmB[v], 1u << l);
    }

    // pack 10 target values (0..31, or 32 if masked) into two words, 6b each
    unsigned int vkp0 = 0u, vkp1 = 0u;
#pragma unroll
    for (int k = 0; k < 10; k++) {
        unsigned int v = n64 ? (n32p[(jbase + k) * 2] & 31u)
                             : (n32p[jbase + k] & 31u);
        bool m = m32 ? (m32p[jbase + k] != 0u) : (mbp[jbase + k] != 0);
        if (!m) v = 32u;
        if (k < 5) vkp0 |= v << (6 * k);
        else       vkp1 |= v << (6 * (k - 5));
    }

    // target exps (MUFU; overlaps row build above)
    float ex[10], ey[10];
#pragma unroll
    for (int q = 0; q < 5; q++) {
        float ta = t2[q].x * 0.2f, tb = t2[q].y * 0.2f;
        ex[2 * q]     = __expf(ta);  ey[2 * q]     = __expf(-ta);
        ex[2 * q + 1] = __expf(tb);  ey[2 * q + 1] = __expf(-tb);
    }
    __syncthreads();

    // ---- phase C: straight-line 2-slot loop, single deferred rare path ----
    const unsigned int* NM = rowA ? nmA : nmB;
    const float2*       S  = rowA ? sA  : sB;
    const int ljbase = half * 10;

    float a0 = 0.0f, a1 = 0.0f;
    unsigned int restflags = 0u;
#pragma unroll
    for (int k = 0; k < 10; k++) {
        const unsigned int vkk = (k < 5 ? (vkp0 >> (6 * k)) : (vkp1 >> (6 * (k - 5)))) & 63u;
        unsigned int bits = NM[vkk];
        const float exk = ex[k], eyk = ey[k];
        const int lj = ljbase + k;

        int li0 = __ffs(bits) - 1;               // empty -> -1 -> S[31]=(0,0)
        unsigned int b1m = bits & (bits - 1);
        int li1 = __ffs(b1m) - 1;
        restflags |= (b1m & (b1m - 1)) ? (1u << k) : 0u;
        {
            float2 sv = S[li0 & 31];
            int d = li0 - lj; d = d < 0 ? -d : d;
            a0 += dvals[d] * fminf(exk * sv.y, eyk * sv.x);
        }
        {
            float2 sv = S[li1 & 31];
            int d = li1 - lj; d = d < 0 ? -d : d;
            a1 += dvals[d] * fminf(exk * sv.y, eyk * sv.x);
        }
    }

    if (restflags) {                             // multiplicity >= 3 (rare)
#pragma unroll 1
        do {
            int k = __ffs(restflags) - 1;
            restflags &= restflags - 1;
            const unsigned int vkk =
                (k < 5 ? (vkp0 >> (6 * k)) : (vkp1 >> (6 * (k - 5)))) & 63u;
            unsigned int bits = NM[vkk];
            bits &= bits - 1;                    // drop slot 0
            bits &= bits - 1;                    // drop slot 1
            const float exk = ex[k], eyk = ey[k];
            const int lj = ljbase + k;
#pragma unroll 1
            do {
                int li = __ffs(bits) - 1;
                bits &= bits - 1;
                float2 sv = S[li];
                int d = li - lj; d = d < 0 ? -d : d;
                a0 += dvals[d] * fminf(exk * sv.y, eyk * sv.x);
            } while (bits);
        } while (restflags);
    }

    // ---- combine halves, tanh, symmetric store (no acc smem, no barrier) ----
    float a = a0 + a1;
    a += __shfl_xor_sync(0xFFFFFFFFu, a, 1);
    if (active && half == 0) {
        const int w1 = rowA ? wA : wB;
        float v = tanh_approx(fminf(a, 10.0f));  // a >= 0; approx err ~1e-4
        out[(b * 128 + w1) * 128 + w2] = v;
        out[(b * 128 + w2) * 128 + w1] = v;
    }
}

extern "C" void kernel_launch(void* const* d_in, const int* in_sizes, int n_in,
                              void* d_out, int out_size)
{
    const void*  nodes = d_in[0];
    const void*  masks = d_in[1];
    const float* times = (const float*)d_in[2];
    float*       out   = (float*)d_out;

    dim3 grid(64, 8);
    cooc_fused<<<grid, BDIM>>>(nodes, masks, times, out);
}